// round 1
// baseline (speedup 1.0000x reference)
#include <cuda_runtime.h>

#define N_KKA 288
#define N_P   512
#define N_LOC 196
#define N_BL  784   // 4 * 196

// 462 MB fp32 scratch for pose_out[bl][kka][p]
__device__ float g_po[(size_t)N_BL * N_KKA * N_P];

// ---------------------------------------------------------------------------
// Kernel A: pose_out[bl, kka, p] = sum_c W[kka, p, c] * x[bl, kka, c]
// x[bl, kka, c] = pose[b, a*8+c, oh+ky-1, ow+kx-1] (zero-padded), kka = kk*32+a
// Grid: (288 kka, 49 location-tiles of 16), 256 threads.
// ---------------------------------------------------------------------------
__global__ void __launch_bounds__(256) pose_out_kernel(
        const float* __restrict__ pose, const float* __restrict__ W) {
    const int kka  = blockIdx.x;
    const int tile = blockIdx.y;
    __shared__ float Wsm[N_P * 9];   // stride 9 pad: conflict-free strided reads
    __shared__ float xsm[16 * 8];
    const int t = threadIdx.x;

    const float* Wk = W + (size_t)kka * (N_P * 8);
    for (int i = t; i < N_P * 8; i += 256)
        Wsm[(i >> 3) * 9 + (i & 7)] = Wk[i];

    if (t < 128) {
        const int blc = t >> 3, c = t & 7;
        const int bl = tile * 16 + blc;
        const int b = bl / N_LOC, l = bl % N_LOC;
        const int oh = l / 14, ow = l % 14;
        const int a = kka & 31, kk = kka >> 5;
        const int ky = kk / 3, kx = kk % 3;
        const int ih = oh + ky - 1, iw = ow + kx - 1;
        float val = 0.f;
        if ((unsigned)ih < 14u && (unsigned)iw < 14u)
            val = pose[((b * 256 + a * 8 + c) * 14 + ih) * 14 + iw];
        xsm[t] = val;
    }
    __syncthreads();

    float w0[8], w1[8];
#pragma unroll
    for (int c = 0; c < 8; c++) {
        w0[c] = Wsm[t * 9 + c];
        w1[c] = Wsm[(t + 256) * 9 + c];
    }
    float* dstbase = g_po + ((size_t)(tile * 16) * N_KKA + kka) * N_P;
#pragma unroll 4
    for (int blc = 0; blc < 16; blc++) {
        float a0 = 0.f, a1 = 0.f;
#pragma unroll
        for (int c = 0; c < 8; c++) {
            const float x = xsm[blc * 8 + c];   // broadcast
            a0 = fmaf(w0[c], x, a0);
            a1 = fmaf(w1[c], x, a1);
        }
        float* dst = dstbase + (size_t)blc * (N_KKA * N_P);
        dst[t]       = a0;   // coalesced over p
        dst[t + 256] = a1;
    }
}

// ---------------------------------------------------------------------------
// Kernel B: fused 3-iteration dynamic routing. One CTA per (b, l) location.
// 512 threads = 16 warps. warp -> k-stripe (kka = i*16 + wid, i=0..17),
// lane -> output capsule bc (0..31), each thread owns all 16 d-values.
// Softmax over bc is a pure intra-warp shuffle reduction. logits in registers.
// ---------------------------------------------------------------------------
__global__ void __launch_bounds__(512) routing_kernel(float* __restrict__ out) {
    __shared__ float sred[16 * 512];   // per-warp partial s, swizzled
    __shared__ float vsm[512];         // v, transposed layout [d][bc]

    const int bl = blockIdx.x;
    const int b = bl / N_LOC, l = bl % N_LOC;
    const int t = threadIdx.x;
    const int wid = t >> 5, lane = t & 31;

    const float* po = g_po + (size_t)bl * (N_KKA * N_P) + lane * 16;

    float v[16];
    float lgs[18];        // logits[kka, lane] for this thread's 18 k's
    float vout = 0.f;

#pragma unroll 1
    for (int pass = 0; pass < 3; pass++) {
        float s[16];
#pragma unroll
        for (int d = 0; d < 16; d++) s[d] = 0.f;

#pragma unroll
        for (int i = 0; i < 18; i++) {
            const int kka = i * 16 + wid;
            const float4* pp = (const float4*)(po + kka * N_P);
            const float4 q0 = pp[0], q1 = pp[1], q2 = pp[2], q3 = pp[3];
            const float r[16] = {q0.x,q0.y,q0.z,q0.w, q1.x,q1.y,q1.z,q1.w,
                                 q2.x,q2.y,q2.z,q2.w, q3.x,q3.y,q3.z,q3.w};
            float cc;
            if (pass == 0) {
                cc = 0.03125f;   // softmax of zeros over 32
            } else {
                float delta = 0.f;
#pragma unroll
                for (int d = 0; d < 16; d++) delta = fmaf(v[d], r[d], delta);
                float lg = (pass == 2) ? (lgs[i] + delta) : delta;
                lgs[i] = lg;
                // softmax over the 32 lanes (bc)
                float m = lg;
#pragma unroll
                for (int off = 16; off; off >>= 1)
                    m = fmaxf(m, __shfl_xor_sync(0xffffffffu, m, off));
                const float e = __expf(lg - m);
                float ssum = e;
#pragma unroll
                for (int off = 16; off; off >>= 1)
                    ssum += __shfl_xor_sync(0xffffffffu, ssum, off);
                cc = __fdividef(e, ssum);
            }
#pragma unroll
            for (int d = 0; d < 16; d++) s[d] = fmaf(cc, r[d], s[d]);
        }

        // cross-warp reduce s: swizzled store -> conflict-free both directions
#pragma unroll
        for (int d = 0; d < 16; d++)
            sred[wid * 512 + lane * 16 + ((d + (lane >> 1)) & 15)] = s[d];
        __syncthreads();

        // thread t owns (bc = t>>4, d = t&15)
        const int bc = t >> 4, d = t & 15;
        float stot = 0.f;
#pragma unroll
        for (int w = 0; w < 16; w++)
            stot += sred[w * 512 + bc * 16 + ((d + (bc >> 1)) & 15)];

        // squash over d (16-thread groups, same half-warp)
        float magsq = stot * stot;
#pragma unroll
        for (int off = 8; off; off >>= 1)
            magsq += __shfl_xor_sync(0xffffffffu, magsq, off);
        const float vv = stot * magsq / ((1.f + magsq) * sqrtf(magsq));

        vsm[d * 32 + bc] = vv;   // transposed: conflict-free reads below
        if (pass == 2) vout = vv;
        __syncthreads();

#pragma unroll
        for (int dd = 0; dd < 16; dd++) v[dd] = vsm[dd * 32 + lane];
    }

    // out[b, p = bc*16+d = t, l]
    out[((size_t)b * N_P + t) * N_LOC + l] = vout;
}

// ---------------------------------------------------------------------------
extern "C" void kernel_launch(void* const* d_in, const int* in_sizes, int n_in,
                              void* d_out, int out_size) {
    const float* pose = (const float*)d_in[0];  // (4, 256, 14, 14)
    const float* W    = (const float*)d_in[1];  // (288, 512, 8)
    float* out = (float*)d_out;                 // (4, 512, 14, 14)

    pose_out_kernel<<<dim3(N_KKA, 49), 256>>>(pose, W);
    routing_kernel<<<N_BL, 512>>>(out);
}

// round 2
// speedup vs baseline: 1.2656x; 1.2656x over previous
#include <cuda_runtime.h>
#include <cuda_fp16.h>

#define N_KKA 288
#define N_P   512
#define N_LOC 196
#define N_BL  784   // 4 * 196

// 231 MB fp16 scratch: pose_out[bl][kka][d2][bc] as half2 (lo = d=2*d2, hi = d=2*d2+1)
__device__ __half2 g_po[(size_t)N_BL * N_KKA * 256];

// ---------------------------------------------------------------------------
// Kernel A: pose_out[bl, kka, p] = sum_c W[kka, p, c] * x[bl, kka, c]
// Output stored transposed (p -> (d2, bc)) and packed half2 so kernel B's
// loads are warp-coalesced. W rows are permuted in smem (slot g(p)) so the
// compute loop still reads Wsm[t*9+c] / Wsm[(t+256)*9+c] conflict-free and
// stores dst[t] coalesced.
// g(p) = ((p&1)<<8) + ((p&15)>>1)*32 + (p>>4);  thread t owns p0(t)=even,
// p1(t)=p0+1 with d2 = t>>5, bc = t&31.
// ---------------------------------------------------------------------------
__global__ void __launch_bounds__(256) pose_out_kernel(
        const float* __restrict__ pose, const float* __restrict__ W) {
    const int kka  = blockIdx.x;
    const int tile = blockIdx.y;
    __shared__ float Wsm[N_P * 9];
    __shared__ float xsm[16 * 8];
    const int t = threadIdx.x;

    const float* Wk = W + (size_t)kka * (N_P * 8);
    for (int i = t; i < N_P * 8; i += 256) {
        const int p = i >> 3, c = i & 7;
        const int slot = ((p & 1) << 8) + ((p & 15) >> 1) * 32 + (p >> 4);
        Wsm[slot * 9 + c] = Wk[i];
    }

    if (t < 128) {
        const int blc = t >> 3, c = t & 7;
        const int bl = tile * 16 + blc;
        const int b = bl / N_LOC, l = bl % N_LOC;
        const int oh = l / 14, ow = l % 14;
        const int a = kka & 31, kk = kka >> 5;
        const int ky = kk / 3, kx = kk % 3;
        const int ih = oh + ky - 1, iw = ow + kx - 1;
        float val = 0.f;
        if ((unsigned)ih < 14u && (unsigned)iw < 14u)
            val = pose[((b * 256 + a * 8 + c) * 14 + ih) * 14 + iw];
        xsm[t] = val;
    }
    __syncthreads();

    float w0[8], w1[8];
#pragma unroll
    for (int c = 0; c < 8; c++) {
        w0[c] = Wsm[t * 9 + c];          // row p0 = (t&31)*16 + 2*(t>>5)
        w1[c] = Wsm[(t + 256) * 9 + c];  // row p1 = p0 + 1
    }
    __half2* dstbase = g_po + ((size_t)(tile * 16) * N_KKA + kka) * 256;
#pragma unroll 4
    for (int blc = 0; blc < 16; blc++) {
        float a0 = 0.f, a1 = 0.f;
#pragma unroll
        for (int c = 0; c < 8; c++) {
            const float x = xsm[blc * 8 + c];   // broadcast
            a0 = fmaf(w0[c], x, a0);
            a1 = fmaf(w1[c], x, a1);
        }
        __half2* dst = dstbase + (size_t)blc * (N_KKA * 256);
        dst[t] = __floats2half2_rn(a0, a1);     // coalesced: slot t = (t>>5)*32+(t&31)
    }
}

// ---------------------------------------------------------------------------
// Kernel B: fused 3-iteration dynamic routing. One CTA per (b, l) location.
// 512 threads = 16 warps. warp -> k-stripe (kka = i*16 + wid), lane -> output
// capsule bc. Loads are half2 at [d2*32 + bc]: each of the 8 loads per k is a
// single fully-coalesced 128B line (vs 16 lines/load in round 1).
// ---------------------------------------------------------------------------
__global__ void __launch_bounds__(512) routing_kernel(float* __restrict__ out) {
    __shared__ float sred[16 * 512];   // per-warp partial s, swizzled
    __shared__ float vsm[512];         // v, transposed layout [d][bc]

    const int bl = blockIdx.x;
    const int b = bl / N_LOC, l = bl % N_LOC;
    const int t = threadIdx.x;
    const int wid = t >> 5, lane = t & 31;

    const __half2* po = g_po + (size_t)bl * (N_KKA * 256) + lane;

    float v[16];
    float lgs[18];        // logits[kka, lane] for this thread's 18 k's
    float vout = 0.f;

#pragma unroll 1
    for (int pass = 0; pass < 3; pass++) {
        float s[16];
#pragma unroll
        for (int d = 0; d < 16; d++) s[d] = 0.f;

#pragma unroll
        for (int i = 0; i < 18; i++) {
            const int kka = i * 16 + wid;
            const __half2* pp = po + kka * 256;
            float r[16];
#pragma unroll
            for (int d2 = 0; d2 < 8; d2++) {
                const float2 f = __half22float2(pp[d2 * 32]);
                r[2 * d2]     = f.x;
                r[2 * d2 + 1] = f.y;
            }
            float cc;
            if (pass == 0) {
                cc = 0.03125f;   // softmax of zeros over 32
            } else {
                float delta = 0.f;
#pragma unroll
                for (int d = 0; d < 16; d++) delta = fmaf(v[d], r[d], delta);
                float lg = (pass == 2) ? (lgs[i] + delta) : delta;
                lgs[i] = lg;
                // softmax over the 32 lanes (bc)
                float m = lg;
#pragma unroll
                for (int off = 16; off; off >>= 1)
                    m = fmaxf(m, __shfl_xor_sync(0xffffffffu, m, off));
                const float e = __expf(lg - m);
                float ssum = e;
#pragma unroll
                for (int off = 16; off; off >>= 1)
                    ssum += __shfl_xor_sync(0xffffffffu, ssum, off);
                cc = __fdividef(e, ssum);
            }
#pragma unroll
            for (int d = 0; d < 16; d++) s[d] = fmaf(cc, r[d], s[d]);
        }

        // cross-warp reduce s: swizzled store -> conflict-free both directions
#pragma unroll
        for (int d = 0; d < 16; d++)
            sred[wid * 512 + lane * 16 + ((d + (lane >> 1)) & 15)] = s[d];
        __syncthreads();

        // thread t owns (bc = t>>4, d = t&15)
        const int bc = t >> 4, d = t & 15;
        float stot = 0.f;
#pragma unroll
        for (int w = 0; w < 16; w++)
            stot += sred[w * 512 + bc * 16 + ((d + (bc >> 1)) & 15)];

        // squash over d (16-thread groups, same half-warp)
        float magsq = stot * stot;
#pragma unroll
        for (int off = 8; off; off >>= 1)
            magsq += __shfl_xor_sync(0xffffffffu, magsq, off);
        const float vv = stot * magsq / ((1.f + magsq) * sqrtf(magsq));

        vsm[d * 32 + bc] = vv;   // transposed: conflict-free reads below
        if (pass == 2) vout = vv;
        __syncthreads();

#pragma unroll
        for (int dd = 0; dd < 16; dd++) v[dd] = vsm[dd * 32 + lane];
    }

    // out[b, p = bc*16+d = t, l]
    out[((size_t)b * N_P + t) * N_LOC + l] = vout;
}

// ---------------------------------------------------------------------------
extern "C" void kernel_launch(void* const* d_in, const int* in_sizes, int n_in,
                              void* d_out, int out_size) {
    const float* pose = (const float*)d_in[0];  // (4, 256, 14, 14)
    const float* W    = (const float*)d_in[1];  // (288, 512, 8)
    float* out = (float*)d_out;                 // (4, 512, 14, 14)

    pose_out_kernel<<<dim3(N_KKA, 49), 256>>>(pose, W);
    routing_kernel<<<N_BL, 512>>>(out);
}

// round 4
// speedup vs baseline: 1.4834x; 1.1721x over previous
#include <cuda_runtime.h>
#include <cuda_fp16.h>

#define N_KKA 288
#define N_P   512
#define N_LOC 196
#define N_BL  784   // 4 * 196
#define TILE  28    // bl per kernel-A CTA (784 = 28*28)

// 231 MB fp16 scratch: pose_out[bl][kka][bc][d] as halves (h2 index = bc*8+d2)
__device__ __half2 g_po[(size_t)N_BL * N_KKA * 256];

// ---------------------------------------------------------------------------
// Kernel A: pose_out[bl, kka, p] = sum_c W[kka, p, c] * x[bl, kka, c]
// Thread t owns p0 = (t>>3)*16 + (t&7)*2 and p1 = p0+1, so its half2 store
// lands at h2 index (bc*8 + d2) = t  (layout [bc][d], coalesced).
// W rows are permuted in smem: slot(p) = ((p&1)<<8) | ((p>>4)<<3) | ((p&15)>>1)
// so thread t reads rows slot==t (w0) and slot==t+256 (w1), stride-9 padded.
// ---------------------------------------------------------------------------
__global__ void __launch_bounds__(256) pose_out_kernel(
        const float* __restrict__ pose, const float* __restrict__ W) {
    const int kka  = blockIdx.x;
    const int tile = blockIdx.y;
    __shared__ float Wsm[N_P * 9];
    __shared__ float xsm[TILE * 8];
    const int t = threadIdx.x;

    // load W slab (16KB) as float4: slab = 512 rows * 8 c = 1024 float4,
    // two float4 per p row.  (round-3 bug: only half was loaded)
    const float4* Wk4 = (const float4*)(W + (size_t)kka * (N_P * 8));
#pragma unroll
    for (int j = 0; j < 4; j++) {
        const int i4 = t + j * 256;
        const float4 w4 = Wk4[i4];
        const int p = i4 >> 1;
        const int cb = (i4 & 1) * 4;
        const int slot = ((p & 1) << 8) | ((p >> 4) << 3) | ((p & 15) >> 1);
        Wsm[slot * 9 + cb + 0] = w4.x;
        Wsm[slot * 9 + cb + 1] = w4.y;
        Wsm[slot * 9 + cb + 2] = w4.z;
        Wsm[slot * 9 + cb + 3] = w4.w;
    }

    if (t < TILE * 8) {
        const int blc = t >> 3, c = t & 7;
        const int bl = tile * TILE + blc;
        const int b = bl / N_LOC, l = bl % N_LOC;
        const int oh = l / 14, ow = l % 14;
        const int a = kka & 31, kk = kka >> 5;
        const int ky = kk / 3, kx = kk % 3;
        const int ih = oh + ky - 1, iw = ow + kx - 1;
        float val = 0.f;
        if ((unsigned)ih < 14u && (unsigned)iw < 14u)
            val = pose[((b * 256 + a * 8 + c) * 14 + ih) * 14 + iw];
        xsm[t] = val;
    }
    __syncthreads();

    float w0[8], w1[8];
#pragma unroll
    for (int c = 0; c < 8; c++) {
        w0[c] = Wsm[t * 9 + c];          // p0
        w1[c] = Wsm[(t + 256) * 9 + c];  // p1 = p0+1
    }
    __half2* dstbase = g_po + ((size_t)(tile * TILE) * N_KKA + kka) * 256;
#pragma unroll 4
    for (int blc = 0; blc < TILE; blc++) {
        float a0 = 0.f, a1 = 0.f;
#pragma unroll
        for (int c = 0; c < 8; c++) {
            const float x = xsm[blc * 8 + c];   // broadcast
            a0 = fmaf(w0[c], x, a0);
            a1 = fmaf(w1[c], x, a1);
        }
        __half2* dst = dstbase + (size_t)blc * (N_KKA * 256);
        dst[t] = __floats2half2_rn(a0, a1);     // coalesced
    }
}

// ---------------------------------------------------------------------------
// Kernel B: fused 3-pass dynamic routing. One 1024-thread CTA per location.
// 32 warps: warp wid handles kka = i*32+wid (i=0..8, lgs[9]); lane = bc;
// each thread owns all 16 d. Loads: 2x LDG.128 per k (layout [kka][bc][d]).
// Softmax: no max subtraction (logits provably tiny), 5-shuffle sum only.
// ---------------------------------------------------------------------------
extern __shared__ float smem_b[];   // sred[32*512] + vsm[16*33]

__global__ void __launch_bounds__(1024, 1) routing_kernel(float* __restrict__ out) {
    float* sred = smem_b;            // 32 warps * 512, swizzled
    float* vsm  = smem_b + 32 * 512; // [d][bc] stride 33

    const int bl = blockIdx.x;
    const int b = bl / N_LOC, l = bl % N_LOC;
    const int t = threadIdx.x;
    const int wid = t >> 5, lane = t & 31;

    const float4* po4 = (const float4*)(g_po + (size_t)bl * (N_KKA * 256) + lane * 8);

    float v[16];
    float lgs[9];
    float vout = 0.f;

#pragma unroll 1
    for (int pass = 0; pass < 3; pass++) {
        float s[16];
#pragma unroll
        for (int d = 0; d < 16; d++) s[d] = 0.f;

#pragma unroll
        for (int i = 0; i < 9; i++) {
            const int kka = i * 32 + wid;
            const float4 q0 = po4[kka * 64];       // 64 float4 per kka
            const float4 q1 = po4[kka * 64 + 1];
            float r[16];
            {
                const __half2* h = (const __half2*)&q0;
#pragma unroll
                for (int j = 0; j < 4; j++) {
                    const float2 f = __half22float2(h[j]);
                    r[2 * j] = f.x; r[2 * j + 1] = f.y;
                }
                const __half2* h1 = (const __half2*)&q1;
#pragma unroll
                for (int j = 0; j < 4; j++) {
                    const float2 f = __half22float2(h1[j]);
                    r[8 + 2 * j] = f.x; r[8 + 2 * j + 1] = f.y;
                }
            }
            float cc;
            if (pass == 0) {
                cc = 0.03125f;   // softmax of zeros over 32
            } else {
                float delta = 0.f;
#pragma unroll
                for (int d = 0; d < 16; d++) delta = fmaf(v[d], r[d], delta);
                const float lg = (pass == 2) ? (lgs[i] + delta) : delta;
                lgs[i] = lg;
                // softmax over 32 lanes; logits are small -> skip max
                const float e = __expf(lg);
                float ssum = e;
#pragma unroll
                for (int off = 16; off; off >>= 1)
                    ssum += __shfl_xor_sync(0xffffffffu, ssum, off);
                cc = __fdividef(e, ssum);
            }
#pragma unroll
            for (int d = 0; d < 16; d++) s[d] = fmaf(cc, r[d], s[d]);
        }

        // cross-warp reduce s: swizzled -> conflict-free both directions
#pragma unroll
        for (int d = 0; d < 16; d++)
            sred[wid * 512 + lane * 16 + ((d + (lane >> 1)) & 15)] = s[d];
        __syncthreads();

        float vv = 0.f;
        const int bc = t >> 4, d = t & 15;
        if (t < 512) {
            float stot = 0.f;
#pragma unroll
            for (int w = 0; w < 32; w++)
                stot += sred[w * 512 + bc * 16 + ((d + (bc >> 1)) & 15)];

            // squash over d (16-thread aligned groups)
            float magsq = stot * stot;
#pragma unroll
            for (int off = 8; off; off >>= 1)
                magsq += __shfl_xor_sync(0xffffffffu, magsq, off);
            vv = stot * magsq / ((1.f + magsq) * sqrtf(magsq));
            vsm[d * 33 + bc] = vv;
            if (pass == 2) vout = vv;
        }
        __syncthreads();

#pragma unroll
        for (int dd = 0; dd < 16; dd++) v[dd] = vsm[dd * 33 + lane];
    }

    if (t < 512)
        out[((size_t)b * N_P + t) * N_LOC + l] = vout;
}

// ---------------------------------------------------------------------------
extern "C" void kernel_launch(void* const* d_in, const int* in_sizes, int n_in,
                              void* d_out, int out_size) {
    const float* pose = (const float*)d_in[0];  // (4, 256, 14, 14)
    const float* W    = (const float*)d_in[1];  // (288, 512, 8)
    float* out = (float*)d_out;                 // (4, 512, 14, 14)

    const int smem_bytes = (32 * 512 + 16 * 33) * (int)sizeof(float);  // ~67.6KB
    cudaFuncSetAttribute(routing_kernel,
                         cudaFuncAttributeMaxDynamicSharedMemorySize, smem_bytes);

    pose_out_kernel<<<dim3(N_KKA, N_BL / TILE), 256>>>(pose, W);
    routing_kernel<<<N_BL, 1024, smem_bytes>>>(out);
}

// round 6
// speedup vs baseline: 1.8697x; 1.2604x over previous
#include <cuda_runtime.h>
#include <cuda_fp16.h>

#define N_KKA 288
#define N_P   512
#define N_LOC 196
#define N_BL  784   // 4 * 196
#define TILE  28    // bl per kernel-A CTA (784 = 28*28)

typedef unsigned long long ull;

// 231 MB fp16 scratch: pose_out[bl][kka][bc][d] as halves (h2 index = bc*8+d2)
__device__ __half2 g_po[(size_t)N_BL * N_KKA * 256];

__device__ __forceinline__ ull ffma2(ull a, ull b, ull c) {
    ull d;
    asm("fma.rn.f32x2 %0, %1, %2, %3;" : "=l"(d) : "l"(a), "l"(b), "l"(c));
    return d;
}
__device__ __forceinline__ ull pack2(float lo, float hi) {
    ull d;
    asm("mov.b64 %0, {%1, %2};" : "=l"(d) : "f"(lo), "f"(hi));
    return d;
}
__device__ __forceinline__ void unpack2(float& lo, float& hi, ull v) {
    asm("mov.b64 {%0, %1}, %2;" : "=f"(lo), "=f"(hi) : "l"(v));
}

// ---------------------------------------------------------------------------
// Kernel A: pose_out[bl, kka, p] = sum_c W[kka, p, c] * x[bl, kka, c]
// Thread t owns p0 = (t>>3)*16 + (t&7)*2 and p1 = p0+1 -> half2 slot t.
// W permuted in smem: slot(p) = ((p&1)<<8) | ((p>>4)<<3) | ((p&15)>>1).
// Compute 2 blc at a time with fma.rn.f32x2: x pair loaded as LDS.64 from
// transposed xsmT[c][blc]; W duplicated into f32x2 regs.
// ---------------------------------------------------------------------------
__global__ void __launch_bounds__(256) pose_out_kernel(
        const float* __restrict__ pose, const float* __restrict__ W) {
    const int kka  = blockIdx.x;
    const int tile = blockIdx.y;
    __shared__ float Wsm[N_P * 9];
    __shared__ float xsmT[8 * TILE];   // [c][blc], 28 floats per row (even)
    const int t = threadIdx.x;

    // load W slab (16KB) as float4: 1024 float4, two per p row
    const float4* Wk4 = (const float4*)(W + (size_t)kka * (N_P * 8));
#pragma unroll
    for (int j = 0; j < 4; j++) {
        const int i4 = t + j * 256;
        const float4 w4 = Wk4[i4];
        const int p = i4 >> 1;
        const int cb = (i4 & 1) * 4;
        const int slot = ((p & 1) << 8) | ((p >> 4) << 3) | ((p & 15) >> 1);
        Wsm[slot * 9 + cb + 0] = w4.x;
        Wsm[slot * 9 + cb + 1] = w4.y;
        Wsm[slot * 9 + cb + 2] = w4.z;
        Wsm[slot * 9 + cb + 3] = w4.w;
    }

    if (t < TILE * 8) {
        const int blc = t >> 3, c = t & 7;
        const int bl = tile * TILE + blc;
        const int b = bl / N_LOC, l = bl % N_LOC;
        const int oh = l / 14, ow = l % 14;
        const int a = kka & 31, kk = kka >> 5;
        const int ky = kk / 3, kx = kk % 3;
        const int ih = oh + ky - 1, iw = ow + kx - 1;
        float val = 0.f;
        if ((unsigned)ih < 14u && (unsigned)iw < 14u)
            val = pose[((b * 256 + a * 8 + c) * 14 + ih) * 14 + iw];
        xsmT[c * TILE + blc] = val;   // transposed
    }
    __syncthreads();

    ull wd0[8], wd1[8];
#pragma unroll
    for (int c = 0; c < 8; c++) {
        const float a0 = Wsm[t * 9 + c];           // p0 row
        const float a1 = Wsm[(t + 256) * 9 + c];   // p1 row
        wd0[c] = pack2(a0, a0);
        wd1[c] = pack2(a1, a1);
    }
    __half2* dstbase = g_po + ((size_t)(tile * TILE) * N_KKA + kka) * 256;
#pragma unroll 2
    for (int pair = 0; pair < TILE / 2; pair++) {
        ull acc0 = 0ull, acc1 = 0ull;   // (blcA, blcB) lanes
#pragma unroll
        for (int c = 0; c < 8; c++) {
            const ull x2 = *(const ull*)&xsmT[c * TILE + pair * 2];  // LDS.64 bcast
            acc0 = ffma2(wd0[c], x2, acc0);
            acc1 = ffma2(wd1[c], x2, acc1);
        }
        float a0A, a0B, a1A, a1B;
        unpack2(a0A, a0B, acc0);
        unpack2(a1A, a1B, acc1);
        __half2* dstA = dstbase + (size_t)(pair * 2) * (N_KKA * 256);
        __half2* dstB = dstA + (N_KKA * 256);
        dstA[t] = __floats2half2_rn(a0A, a1A);
        dstB[t] = __floats2half2_rn(a0B, a1B);
    }
}

// ---------------------------------------------------------------------------
// Kernel B: fused 3-pass dynamic routing. One 1024-thread CTA per location.
// 32 warps: warp wid handles kka = i*32+wid (i=0..8); lane = bc; thread owns
// all 16 d as 8 half2. Whole k-loop in half2 math (HFMA2); softmax lane-sum
// via 5-step shfl butterfly (redux.f32 doesn't exist on sm_103).
// ---------------------------------------------------------------------------
extern __shared__ float smem_b[];   // sred[32*512] fp32 + vsm_h[512] half

__global__ void __launch_bounds__(1024, 1) routing_kernel(float* __restrict__ out) {
    float*  sred  = smem_b;                      // 32 warps * 512, swizzled
    __half* vsm_h = (__half*)(smem_b + 32 * 512);

    const int bl = blockIdx.x;
    const int b = bl / N_LOC, l = bl % N_LOC;
    const int t = threadIdx.x;
    const int wid = t >> 5, lane = t & 31;

    const float4* po4 = (const float4*)(g_po + (size_t)bl * (N_KKA * 256) + lane * 8);

    __half2 v2[8];
    float lgs[9];
    float vout = 0.f;

#pragma unroll 1
    for (int pass = 0; pass < 3; pass++) {
        __half2 s2[8];
#pragma unroll
        for (int j = 0; j < 8; j++) s2[j] = __float2half2_rn(0.f);

#pragma unroll
        for (int i = 0; i < 9; i++) {
            const int kka = i * 32 + wid;
            const float4 q0 = po4[kka * 64];       // 64 float4 per kka
            const float4 q1 = po4[kka * 64 + 1];
            __half2 r2[8];
            {
                const __half2* h0 = (const __half2*)&q0;
                const __half2* h1 = (const __half2*)&q1;
#pragma unroll
                for (int j = 0; j < 4; j++) { r2[j] = h0[j]; r2[4 + j] = h1[j]; }
            }
            __half2 c2;
            if (pass == 0) {
                c2 = __float2half2_rn(0.03125f);   // softmax of zeros over 32
            } else {
                __half2 acc0 = __hmul2(v2[0], r2[0]);
                acc0 = __hfma2(v2[1], r2[1], acc0);
                acc0 = __hfma2(v2[2], r2[2], acc0);
                acc0 = __hfma2(v2[3], r2[3], acc0);
                __half2 acc1 = __hmul2(v2[4], r2[4]);
                acc1 = __hfma2(v2[5], r2[5], acc1);
                acc1 = __hfma2(v2[6], r2[6], acc1);
                acc1 = __hfma2(v2[7], r2[7], acc1);
                const float2 df = __half22float2(__hadd2(acc0, acc1));
                const float delta = df.x + df.y;
                const float lg = (pass == 2) ? (lgs[i] + delta) : delta;
                lgs[i] = lg;
                // softmax over 32 lanes; logits tiny -> no max subtraction
                const float e = __expf(lg);
                float ssum = e;
#pragma unroll
                for (int off = 16; off; off >>= 1)
                    ssum += __shfl_xor_sync(0xffffffffu, ssum, off);
                c2 = __half2half2(__float2half_rn(__fdividef(e, ssum)));
            }
#pragma unroll
            for (int j = 0; j < 8; j++) s2[j] = __hfma2(c2, r2[j], s2[j]);
        }

        // cross-warp reduce s: fp32 smem, swizzled -> conflict-free both ways
#pragma unroll
        for (int j = 0; j < 8; j++) {
            const float2 f = __half22float2(s2[j]);
            const int d0 = 2 * j, d1 = 2 * j + 1;
            sred[wid * 512 + lane * 16 + ((d0 + (lane >> 1)) & 15)] = f.x;
            sred[wid * 512 + lane * 16 + ((d1 + (lane >> 1)) & 15)] = f.y;
        }
        __syncthreads();

        if (t < 512) {
            const int bc = t >> 4, d = t & 15;
            float stot = 0.f;
#pragma unroll
            for (int w = 0; w < 32; w++)
                stot += sred[w * 512 + bc * 16 + ((d + (bc >> 1)) & 15)];

            // squash over d (16-thread aligned groups)
            float magsq = stot * stot;
#pragma unroll
            for (int off = 8; off; off >>= 1)
                magsq += __shfl_xor_sync(0xffffffffu, magsq, off);
            const float vv = stot * magsq / ((1.f + magsq) * sqrtf(magsq));
            vsm_h[t] = __float2half_rn(vv);       // layout [bc][d] = index t
            if (pass == 2) vout = vv;
        }
        __syncthreads();

        const __half2* vh2 = (const __half2*)vsm_h;
#pragma unroll
        for (int j = 0; j < 8; j++) v2[j] = vh2[lane * 8 + j];
    }

    if (t < 512)
        out[((size_t)b * N_P + t) * N_LOC + l] = vout;
}

// ---------------------------------------------------------------------------
extern "C" void kernel_launch(void* const* d_in, const int* in_sizes, int n_in,
                              void* d_out, int out_size) {
    const float* pose = (const float*)d_in[0];  // (4, 256, 14, 14)
    const float* W    = (const float*)d_in[1];  // (288, 512, 8)
    float* out = (float*)d_out;                 // (4, 512, 14, 14)

    const int smem_bytes = 32 * 512 * (int)sizeof(float) + 512 * (int)sizeof(__half);
    cudaFuncSetAttribute(routing_kernel,
                         cudaFuncAttributeMaxDynamicSharedMemorySize, smem_bytes);

    pose_out_kernel<<<dim3(N_KKA, N_BL / TILE), 256>>>(pose, W);
    routing_kernel<<<N_BL, 1024, smem_bytes>>>(out);
}

// round 7
// speedup vs baseline: 1.9794x; 1.0587x over previous
#include <cuda_runtime.h>
#include <cuda_fp16.h>

#define N_KKA 288
#define N_P   512
#define N_LOC 196
#define N_BL  784   // 4 * 196
#define TILE  56    // bl per kernel-A CTA (784 = 56*14)

typedef unsigned long long ull;

// 231 MB fp16 scratch, chunk-interleaved: half index =
//   kka*512 + j*256 + bc*8 + dd   (d = j*8+dd, j=0..1)
// so each thread's 8-half chunk is lane-contiguous across the warp in kernel B.
__device__ __half2 g_po[(size_t)N_BL * N_KKA * 256];

__device__ __forceinline__ ull ffma2(ull a, ull b, ull c) {
    ull d;
    asm("fma.rn.f32x2 %0, %1, %2, %3;" : "=l"(d) : "l"(a), "l"(b), "l"(c));
    return d;
}
__device__ __forceinline__ ull pack2(float lo, float hi) {
    ull d;
    asm("mov.b64 %0, {%1, %2};" : "=l"(d) : "f"(lo), "f"(hi));
    return d;
}
__device__ __forceinline__ void unpack2(float& lo, float& hi, ull v) {
    asm("mov.b64 {%0, %1}, %2;" : "=f"(lo), "=f"(hi) : "l"(v));
}

// ---------------------------------------------------------------------------
// Kernel A: pose_out[bl, kka, p] = sum_c W[kka, p, c] * x[bl, kka, c]
// Thread t: bc = t>>3, low3 = t&7, d0 = 2*low3; owns p0 = bc*16+d0, p1 = p0+1.
// Its half2 (p0,p1) lands at h2 slot = ((t&4)<<5) | ((t>>3)<<2) | (t&3)
// within the kka block (chunk-interleaved layout above).
// W permuted in smem: slot(p) = ((p&1)<<8) | ((p>>4)<<3) | ((p&15)>>1).
// 2 blc at a time with fma.rn.f32x2 from transposed xsmT[c][blc] (LDS.64).
// ---------------------------------------------------------------------------
__global__ void __launch_bounds__(256) pose_out_kernel(
        const float* __restrict__ pose, const float* __restrict__ W) {
    const int kka  = blockIdx.x;
    const int tile = blockIdx.y;
    __shared__ float Wsm[N_P * 9];
    __shared__ float xsmT[8 * TILE];   // [c][blc], rows 56 floats (8B-aligned)
    const int t = threadIdx.x;

    // load W slab (16KB) as float4: 1024 float4, two per p row
    const float4* Wk4 = (const float4*)(W + (size_t)kka * (N_P * 8));
#pragma unroll
    for (int j = 0; j < 4; j++) {
        const int i4 = t + j * 256;
        const float4 w4 = Wk4[i4];
        const int p = i4 >> 1;
        const int cb = (i4 & 1) * 4;
        const int slot = ((p & 1) << 8) | ((p >> 4) << 3) | ((p & 15) >> 1);
        Wsm[slot * 9 + cb + 0] = w4.x;
        Wsm[slot * 9 + cb + 1] = w4.y;
        Wsm[slot * 9 + cb + 2] = w4.z;
        Wsm[slot * 9 + cb + 3] = w4.w;
    }

    const int a = kka & 31, kk = kka >> 5;
    const int ky = kk / 3, kx = kk % 3;
#pragma unroll
    for (int idx = t; idx < TILE * 8; idx += 256) {
        const int blc = idx >> 3, c = idx & 7;
        const int bl = tile * TILE + blc;
        const int b = bl / N_LOC, l = bl % N_LOC;
        const int oh = l / 14, ow = l % 14;
        const int ih = oh + ky - 1, iw = ow + kx - 1;
        float val = 0.f;
        if ((unsigned)ih < 14u && (unsigned)iw < 14u)
            val = pose[((b * 256 + a * 8 + c) * 14 + ih) * 14 + iw];
        xsmT[c * TILE + blc] = val;   // transposed
    }
    __syncthreads();

    ull wd0[8], wd1[8];
#pragma unroll
    for (int c = 0; c < 8; c++) {
        const float a0 = Wsm[t * 9 + c];           // p0 row
        const float a1 = Wsm[(t + 256) * 9 + c];   // p1 row
        wd0[c] = pack2(a0, a0);
        wd1[c] = pack2(a1, a1);
    }
    const int slot_t = ((t & 4) << 5) | ((t >> 3) << 2) | (t & 3);
    __half2* dstbase = g_po + ((size_t)(tile * TILE) * N_KKA + kka) * 256 + slot_t;
#pragma unroll 2
    for (int pair = 0; pair < TILE / 2; pair++) {
        ull acc0 = 0ull, acc1 = 0ull;   // (blcA, blcB) lanes
#pragma unroll
        for (int c = 0; c < 8; c++) {
            const ull x2 = *(const ull*)&xsmT[c * TILE + pair * 2];  // LDS.64 bcast
            acc0 = ffma2(wd0[c], x2, acc0);
            acc1 = ffma2(wd1[c], x2, acc1);
        }
        float a0A, a0B, a1A, a1B;
        unpack2(a0A, a0B, acc0);
        unpack2(a1A, a1B, acc1);
        __half2* dstA = dstbase + (size_t)(pair * 2) * (N_KKA * 256);
        __half2* dstB = dstA + (N_KKA * 256);
        *dstA = __floats2half2_rn(a0A, a1A);
        *dstB = __floats2half2_rn(a0B, a1B);
    }
}

// ---------------------------------------------------------------------------
// Kernel B: fused 3-pass dynamic routing. One 1024-thread CTA per location.
// 32 warps: warp wid handles kka = i*32+wid (i=0..8); lane = bc; thread owns
// all 16 d as 8 half2. k-loop in half2 math (HFMA2); loads are 2 LDG.128,
// lane-contiguous (4 full 128B lines per warp request).
// ---------------------------------------------------------------------------
extern __shared__ float smem_b[];   // sred[32*512] fp32 + vsm_h[512] half

__global__ void __launch_bounds__(1024, 1) routing_kernel(float* __restrict__ out) {
    float*  sred  = smem_b;                      // 32 warps * 512, swizzled
    __half* vsm_h = (__half*)(smem_b + 32 * 512);

    const int bl = blockIdx.x;
    const int b = bl / N_LOC, l = bl % N_LOC;
    const int t = threadIdx.x;
    const int wid = t >> 5, lane = t & 31;

    const float4* po4 = (const float4*)(g_po + (size_t)bl * (N_KKA * 256));

    __half2 v2[8];
    float lgs[9];
    float vout = 0.f;

#pragma unroll 1
    for (int pass = 0; pass < 3; pass++) {
        __half2 s2[8];
#pragma unroll
        for (int j = 0; j < 8; j++) s2[j] = __float2half2_rn(0.f);

#pragma unroll
        for (int i = 0; i < 9; i++) {
            const int kka = i * 32 + wid;
            const float4 q0 = po4[kka * 64 + lane];        // j=0 chunk: d 0..7
            const float4 q1 = po4[kka * 64 + 32 + lane];   // j=1 chunk: d 8..15
            __half2 r2[8];
            {
                const __half2* h0 = (const __half2*)&q0;
                const __half2* h1 = (const __half2*)&q1;
#pragma unroll
                for (int j = 0; j < 4; j++) { r2[j] = h0[j]; r2[4 + j] = h1[j]; }
            }
            __half2 c2;
            if (pass == 0) {
                c2 = __float2half2_rn(0.03125f);   // softmax of zeros over 32
            } else {
                __half2 acc0 = __hmul2(v2[0], r2[0]);
                acc0 = __hfma2(v2[1], r2[1], acc0);
                acc0 = __hfma2(v2[2], r2[2], acc0);
                acc0 = __hfma2(v2[3], r2[3], acc0);
                __half2 acc1 = __hmul2(v2[4], r2[4]);
                acc1 = __hfma2(v2[5], r2[5], acc1);
                acc1 = __hfma2(v2[6], r2[6], acc1);
                acc1 = __hfma2(v2[7], r2[7], acc1);
                const float2 df = __half22float2(__hadd2(acc0, acc1));
                const float delta = df.x + df.y;
                const float lg = (pass == 2) ? (lgs[i] + delta) : delta;
                lgs[i] = lg;
                // softmax over 32 lanes; logits tiny -> no max subtraction
                const float e = __expf(lg);
                float ssum = e;
#pragma unroll
                for (int off = 16; off; off >>= 1)
                    ssum += __shfl_xor_sync(0xffffffffu, ssum, off);
                c2 = __half2half2(__float2half_rn(__fdividef(e, ssum)));
            }
#pragma unroll
            for (int j = 0; j < 8; j++) s2[j] = __hfma2(c2, r2[j], s2[j]);
        }

        // cross-warp reduce s: fp32 smem, swizzled -> conflict-free both ways
#pragma unroll
        for (int j = 0; j < 8; j++) {
            const float2 f = __half22float2(s2[j]);
            const int d0 = 2 * j, d1 = 2 * j + 1;
            sred[wid * 512 + lane * 16 + ((d0 + (lane >> 1)) & 15)] = f.x;
            sred[wid * 512 + lane * 16 + ((d1 + (lane >> 1)) & 15)] = f.y;
        }
        __syncthreads();

        if (t < 512) {
            const int bc = t >> 4, d = t & 15;
            float stot = 0.f;
#pragma unroll
            for (int w = 0; w < 32; w++)
                stot += sred[w * 512 + bc * 16 + ((d + (bc >> 1)) & 15)];

            // squash over d (16-thread aligned groups)
            float magsq = stot * stot;
#pragma unroll
            for (int off = 8; off; off >>= 1)
                magsq += __shfl_xor_sync(0xffffffffu, magsq, off);
            const float vv = stot * magsq / ((1.f + magsq) * sqrtf(magsq));
            vsm_h[t] = __float2half_rn(vv);       // layout [bc][d] = index t
            if (pass == 2) vout = vv;
        }
        __syncthreads();

        const __half2* vh2 = (const __half2*)vsm_h;
#pragma unroll
        for (int j = 0; j < 8; j++) v2[j] = vh2[lane * 8 + j];
    }

    if (t < 512)
        out[((size_t)b * N_P + t) * N_LOC + l] = vout;
}

// ---------------------------------------------------------------------------
extern "C" void kernel_launch(void* const* d_in, const int* in_sizes, int n_in,
                              void* d_out, int out_size) {
    const float* pose = (const float*)d_in[0];  // (4, 256, 14, 14)
    const float* W    = (const float*)d_in[1];  // (288, 512, 8)
    float* out = (float*)d_out;                 // (4, 512, 14, 14)

    const int smem_bytes = 32 * 512 * (int)sizeof(float) + 512 * (int)sizeof(__half);
    cudaFuncSetAttribute(routing_kernel,
                         cudaFuncAttributeMaxDynamicSharedMemorySize, smem_bytes);

    pose_out_kernel<<<dim3(N_KKA, N_BL / TILE), 256>>>(pose, W);
    routing_kernel<<<N_BL, 1024, smem_bytes>>>(out);
}

// round 8
// speedup vs baseline: 2.1088x; 1.0654x over previous
#include <cuda_runtime.h>
#include <cuda_fp16.h>

#define N_KKA 288
#define N_P   512
#define N_LOC 196
#define N_BL  784   // 4 * 196
#define TILE  56    // bl per kernel-A CTA (784 = 56*14)

#define CACHED_W 20          // warps 0..19 cache their po slice in smem
#define SRED_STRIDE 1028     // h2 units; pad 4 -> conflict-free read banks

typedef unsigned long long ull;

// 231 MB fp16 scratch, chunk-interleaved: half index =
//   kka*512 + j*256 + bc*8 + dd   (d = j*8+dd, j=0..1)
__device__ __half2 g_po[(size_t)N_BL * N_KKA * 256];

__device__ __forceinline__ ull ffma2(ull a, ull b, ull c) {
    ull d;
    asm("fma.rn.f32x2 %0, %1, %2, %3;" : "=l"(d) : "l"(a), "l"(b), "l"(c));
    return d;
}
__device__ __forceinline__ ull pack2(float lo, float hi) {
    ull d;
    asm("mov.b64 %0, {%1, %2};" : "=l"(d) : "f"(lo), "f"(hi));
    return d;
}
__device__ __forceinline__ void unpack2(float& lo, float& hi, ull v) {
    asm("mov.b64 {%0, %1}, %2;" : "=f"(lo), "=f"(hi) : "l"(v));
}

// ---------------------------------------------------------------------------
// Kernel A: unchanged from round 7 (traffic-bound; tackled next round).
// ---------------------------------------------------------------------------
__global__ void __launch_bounds__(256) pose_out_kernel(
        const float* __restrict__ pose, const float* __restrict__ W) {
    const int kka  = blockIdx.x;
    const int tile = blockIdx.y;
    __shared__ float Wsm[N_P * 9];
    __shared__ float xsmT[8 * TILE];   // [c][blc]
    const int t = threadIdx.x;

    const float4* Wk4 = (const float4*)(W + (size_t)kka * (N_P * 8));
#pragma unroll
    for (int j = 0; j < 4; j++) {
        const int i4 = t + j * 256;
        const float4 w4 = Wk4[i4];
        const int p = i4 >> 1;
        const int cb = (i4 & 1) * 4;
        const int slot = ((p & 1) << 8) | ((p >> 4) << 3) | ((p & 15) >> 1);
        Wsm[slot * 9 + cb + 0] = w4.x;
        Wsm[slot * 9 + cb + 1] = w4.y;
        Wsm[slot * 9 + cb + 2] = w4.z;
        Wsm[slot * 9 + cb + 3] = w4.w;
    }

    const int a = kka & 31, kk = kka >> 5;
    const int ky = kk / 3, kx = kk % 3;
#pragma unroll
    for (int idx = t; idx < TILE * 8; idx += 256) {
        const int blc = idx >> 3, c = idx & 7;
        const int bl = tile * TILE + blc;
        const int b = bl / N_LOC, l = bl % N_LOC;
        const int oh = l / 14, ow = l % 14;
        const int ih = oh + ky - 1, iw = ow + kx - 1;
        float val = 0.f;
        if ((unsigned)ih < 14u && (unsigned)iw < 14u)
            val = pose[((b * 256 + a * 8 + c) * 14 + ih) * 14 + iw];
        xsmT[c * TILE + blc] = val;
    }
    __syncthreads();

    ull wd0[8], wd1[8];
#pragma unroll
    for (int c = 0; c < 8; c++) {
        const float a0 = Wsm[t * 9 + c];
        const float a1 = Wsm[(t + 256) * 9 + c];
        wd0[c] = pack2(a0, a0);
        wd1[c] = pack2(a1, a1);
    }
    const int slot_t = ((t & 4) << 5) | ((t >> 3) << 2) | (t & 3);
    __half2* dstbase = g_po + ((size_t)(tile * TILE) * N_KKA + kka) * 256 + slot_t;
#pragma unroll 2
    for (int pair = 0; pair < TILE / 2; pair++) {
        ull acc0 = 0ull, acc1 = 0ull;
#pragma unroll
        for (int c = 0; c < 8; c++) {
            const ull x2 = *(const ull*)&xsmT[c * TILE + pair * 2];
            acc0 = ffma2(wd0[c], x2, acc0);
            acc1 = ffma2(wd1[c], x2, acc1);
        }
        float a0A, a0B, a1A, a1B;
        unpack2(a0A, a0B, acc0);
        unpack2(a1A, a1B, acc1);
        __half2* dstA = dstbase + (size_t)(pair * 2) * (N_KKA * 256);
        __half2* dstB = dstA + (N_KKA * 256);
        *dstA = __floats2half2_rn(a0A, a1A);
        *dstB = __floats2half2_rn(a0B, a1B);
    }
}

// ---------------------------------------------------------------------------
// Kernel B helpers
// ---------------------------------------------------------------------------
__device__ __forceinline__ float softmax_c(float lg) {
    // e^lg scaled by 2^16, u32 hardware redux across 32 lanes; scale cancels.
    float es;
    {
        const float x = fmaf(lg, 1.44269504f, 16.0f);
        asm("ex2.approx.f32 %0, %1;" : "=f"(es) : "f"(x));
    }
    const unsigned ei = __float2uint_rn(es);
    unsigned si;
    asm("redux.sync.add.u32 %0, %1, 0xffffffff;" : "=r"(si) : "r"(ei));
    return __fdividef(es, __uint2float_rn(si));
}

// cross-warp s reduce + squash + broadcast; returns vv (valid for t<512)
__device__ __forceinline__ float reduce_squash(
        __half2* sred, __half* vsm_h, const __half2 s2[8], __half2 v2[8],
        int t, int wid, int lane) {
#pragma unroll
    for (int j = 0; j < 8; j++)
        sred[j * SRED_STRIDE + wid * 32 + lane] = s2[j];
    __syncthreads();
    float vv = 0.f;
    if (t < 512) {
        const int bc = t >> 4, d = t & 15, j = d >> 1;
        float stot = 0.f;
#pragma unroll
        for (int w = 0; w < 32; w++) {
            const float2 f = __half22float2(sred[j * SRED_STRIDE + w * 32 + bc]);
            stot += (d & 1) ? f.y : f.x;
        }
        float magsq = stot * stot;
#pragma unroll
        for (int off = 8; off; off >>= 1)
            magsq += __shfl_xor_sync(0xffffffffu, magsq, off);
        vv = stot * magsq / ((1.f + magsq) * sqrtf(magsq));
        vsm_h[t] = __float2half_rn(vv);
    }
    __syncthreads();
    const __half2* vh2 = (const __half2*)vsm_h;
#pragma unroll
    for (int j = 0; j < 8; j++) v2[j] = vh2[lane * 8 + j];
    return vv;
}

// ---------------------------------------------------------------------------
// Kernel B: fused 3-pass routing, 1024 threads per location. Warps 0..19
// cache their 180 kka (180KB) in smem during pass 0; passes 1-2 read LDS.
// Softmax lane-sum via fixed-point redux.sync.add.u32.
// smem: cache 184320B | sred(h2, stride 1028) 32896B | vsm(half) 1024B
// ---------------------------------------------------------------------------
extern __shared__ char smem_raw[];

__global__ void __launch_bounds__(1024, 1) routing_kernel(float* __restrict__ out) {
    float4*  cache4 = (float4*)smem_raw;                       // 180 kka * 64 f4
    __half2* sred   = (__half2*)(smem_raw + 184320);
    __half*  vsm_h  = (__half*)(smem_raw + 217216);

    const int bl = blockIdx.x;
    const int b = bl / N_LOC, l = bl % N_LOC;
    const int t = threadIdx.x;
    const int wid = t >> 5, lane = t & 31;
    const bool cached = (wid < CACHED_W);

    const float4* po4 = (const float4*)(g_po + (size_t)bl * (N_KKA * 256));

    __half2 v2[8];
    float lgs[9];

    // ---------------- pass 0: c = 1/32, stash cached slices ----------------
    {
        __half2 s2[8];
#pragma unroll
        for (int j = 0; j < 8; j++) s2[j] = __float2half2_rn(0.f);
        const __half2 c2 = __float2half2_rn(0.03125f);
#pragma unroll
        for (int i = 0; i < 9; i++) {
            const int kka = i * 32 + wid;
            const float4 q0 = po4[kka * 64 + lane];
            const float4 q1 = po4[kka * 64 + 32 + lane];
            if (cached) {
                const int slot = (i * CACHED_W + wid) * 64;
                cache4[slot + lane]      = q0;
                cache4[slot + 32 + lane] = q1;
            }
            const __half2* h0 = (const __half2*)&q0;
            const __half2* h1 = (const __half2*)&q1;
#pragma unroll
            for (int j = 0; j < 4; j++) {
                s2[j]     = __hfma2(c2, h0[j], s2[j]);
                s2[4 + j] = __hfma2(c2, h1[j], s2[4 + j]);
            }
        }
        reduce_squash(sred, vsm_h, s2, v2, t, wid, lane);
    }

    // ---------------- passes 1 and 2 ----------------
    float vout = 0.f;
#pragma unroll 1
    for (int pass = 1; pass < 3; pass++) {
        __half2 s2[8];
#pragma unroll
        for (int j = 0; j < 8; j++) s2[j] = __float2half2_rn(0.f);

#pragma unroll
        for (int i = 0; i < 9; i++) {
            float4 q0, q1;
            if (cached) {
                const int slot = (i * CACHED_W + wid) * 64;
                q0 = cache4[slot + lane];
                q1 = cache4[slot + 32 + lane];
            } else {
                const int kka = i * 32 + wid;
                q0 = po4[kka * 64 + lane];
                q1 = po4[kka * 64 + 32 + lane];
            }
            __half2 r2[8];
            {
                const __half2* h0 = (const __half2*)&q0;
                const __half2* h1 = (const __half2*)&q1;
#pragma unroll
                for (int j = 0; j < 4; j++) { r2[j] = h0[j]; r2[4 + j] = h1[j]; }
            }
            __half2 acc0 = __hmul2(v2[0], r2[0]);
            acc0 = __hfma2(v2[1], r2[1], acc0);
            acc0 = __hfma2(v2[2], r2[2], acc0);
            acc0 = __hfma2(v2[3], r2[3], acc0);
            __half2 acc1 = __hmul2(v2[4], r2[4]);
            acc1 = __hfma2(v2[5], r2[5], acc1);
            acc1 = __hfma2(v2[6], r2[6], acc1);
            acc1 = __hfma2(v2[7], r2[7], acc1);
            const float2 df = __half22float2(__hadd2(acc0, acc1));
            const float delta = df.x + df.y;
            const float lg = (pass == 2) ? (lgs[i] + delta) : delta;
            lgs[i] = lg;
            const __half2 c2 = __half2half2(__float2half_rn(softmax_c(lg)));
#pragma unroll
            for (int j = 0; j < 8; j++) s2[j] = __hfma2(c2, r2[j], s2[j]);
        }

        const float vv = reduce_squash(sred, vsm_h, s2, v2, t, wid, lane);
        if (pass == 2) vout = vv;
    }

    if (t < 512)
        out[((size_t)b * N_P + t) * N_LOC + l] = vout;
}

// ---------------------------------------------------------------------------
extern "C" void kernel_launch(void* const* d_in, const int* in_sizes, int n_in,
                              void* d_out, int out_size) {
    const float* pose = (const float*)d_in[0];  // (4, 256, 14, 14)
    const float* W    = (const float*)d_in[1];  // (288, 512, 8)
    float* out = (float*)d_out;                 // (4, 512, 14, 14)

    const int smem_bytes = 218240;  // cache 184320 + sred 32896 + vsm 1024
    cudaFuncSetAttribute(routing_kernel,
                         cudaFuncAttributeMaxDynamicSharedMemorySize, smem_bytes);

    pose_out_kernel<<<dim3(N_KKA, N_BL / TILE), 256>>>(pose, W);
    routing_kernel<<<N_BL, 1024, smem_bytes>>>(out);
}

// round 10
// speedup vs baseline: 2.1652x; 1.0267x over previous
#include <cuda_runtime.h>
#include <cuda_fp16.h>

#define N_KKA 288
#define N_P   512
#define N_LOC 196
#define N_BL  784   // 4 * 196
#define TILE  56    // bl per kernel-A CTA (784 = 56*14)

#define CACHED_W 20          // warps 0..19 cache their po slice in smem
#define SRED_ST  1026        // h2 stride

typedef unsigned long long ull;

// 231 MB fp16 scratch, chunk-interleaved: half index =
//   kka*512 + j*256 + bc*8 + dd   (d = j*8+dd, j=0..1)
__device__ __half2 g_po[(size_t)N_BL * N_KKA * 256];

__device__ __forceinline__ ull ffma2(ull a, ull b, ull c) {
    ull d;
    asm("fma.rn.f32x2 %0, %1, %2, %3;" : "=l"(d) : "l"(a), "l"(b), "l"(c));
    return d;
}
__device__ __forceinline__ ull pack2(float lo, float hi) {
    ull d;
    asm("mov.b64 %0, {%1, %2};" : "=l"(d) : "f"(lo), "f"(hi));
    return d;
}
__device__ __forceinline__ void unpack2(float& lo, float& hi, ull v) {
    asm("mov.b64 {%0, %1}, %2;" : "=f"(lo), "=f"(hi) : "l"(v));
}

// ---------------------------------------------------------------------------
// Kernel A: unchanged from round 7/8.
// ---------------------------------------------------------------------------
__global__ void __launch_bounds__(256) pose_out_kernel(
        const float* __restrict__ pose, const float* __restrict__ W) {
    const int kka  = blockIdx.x;
    const int tile = blockIdx.y;
    __shared__ float Wsm[N_P * 9];
    __shared__ float xsmT[8 * TILE];   // [c][blc]
    const int t = threadIdx.x;

    const float4* Wk4 = (const float4*)(W + (size_t)kka * (N_P * 8));
#pragma unroll
    for (int j = 0; j < 4; j++) {
        const int i4 = t + j * 256;
        const float4 w4 = Wk4[i4];
        const int p = i4 >> 1;
        const int cb = (i4 & 1) * 4;
        const int slot = ((p & 1) << 8) | ((p >> 4) << 3) | ((p & 15) >> 1);
        Wsm[slot * 9 + cb + 0] = w4.x;
        Wsm[slot * 9 + cb + 1] = w4.y;
        Wsm[slot * 9 + cb + 2] = w4.z;
        Wsm[slot * 9 + cb + 3] = w4.w;
    }

    const int a = kka & 31, kk = kka >> 5;
    const int ky = kk / 3, kx = kk % 3;
#pragma unroll
    for (int idx = t; idx < TILE * 8; idx += 256) {
        const int blc = idx >> 3, c = idx & 7;
        const int bl = tile * TILE + blc;
        const int b = bl / N_LOC, l = bl % N_LOC;
        const int oh = l / 14, ow = l % 14;
        const int ih = oh + ky - 1, iw = ow + kx - 1;
        float val = 0.f;
        if ((unsigned)ih < 14u && (unsigned)iw < 14u)
            val = pose[((b * 256 + a * 8 + c) * 14 + ih) * 14 + iw];
        xsmT[c * TILE + blc] = val;
    }
    __syncthreads();

    ull wd0[8], wd1[8];
#pragma unroll
    for (int c = 0; c < 8; c++) {
        const float a0 = Wsm[t * 9 + c];
        const float a1 = Wsm[(t + 256) * 9 + c];
        wd0[c] = pack2(a0, a0);
        wd1[c] = pack2(a1, a1);
    }
    const int slot_t = ((t & 4) << 5) | ((t >> 3) << 2) | (t & 3);
    __half2* dstbase = g_po + ((size_t)(tile * TILE) * N_KKA + kka) * 256 + slot_t;
#pragma unroll 2
    for (int pair = 0; pair < TILE / 2; pair++) {
        ull acc0 = 0ull, acc1 = 0ull;
#pragma unroll
        for (int c = 0; c < 8; c++) {
            const ull x2 = *(const ull*)&xsmT[c * TILE + pair * 2];
            acc0 = ffma2(wd0[c], x2, acc0);
            acc1 = ffma2(wd1[c], x2, acc1);
        }
        float a0A, a0B, a1A, a1B;
        unpack2(a0A, a0B, acc0);
        unpack2(a1A, a1B, acc1);
        __half2* dstA = dstbase + (size_t)(pair * 2) * (N_KKA * 256);
        __half2* dstB = dstA + (N_KKA * 256);
        *dstA = __floats2half2_rn(a0A, a1A);
        *dstB = __floats2half2_rn(a0B, a1B);
    }
}

// ---------------------------------------------------------------------------
// Kernel B helpers
// ---------------------------------------------------------------------------
__device__ __forceinline__ float softmax_c(float lg) {
    // e^lg scaled by 2^16, u32 hardware redux across 32 lanes; scale cancels.
    float es;
    {
        const float x = fmaf(lg, 1.44269504f, 16.0f);
        asm("ex2.approx.f32 %0, %1;" : "=f"(es) : "f"(x));
    }
    const unsigned ei = __float2uint_rn(es);
    unsigned si;
    asm("redux.sync.add.u32 %0, %1, 0xffffffff;" : "=r"(si) : "r"(ei));
    return __fdividef(es, __uint2float_rn(si));
}

// smem layout (bytes):
//   cache4 : 0        .. 184320   (180 kka * 64 float4)
//   sred   : 184320   .. +8*SRED_ST*4 = 32832 -> 217152
//   ppart  : 217152   .. +2048 -> 219200   (512 floats)
//   vsm    : 219200   .. +1152 -> 220352   (32 bc * 18 halves)
#define SM_SRED  184320
#define SM_PPART 217152
#define SM_VSM   219200
#define SM_TOTAL 220352

// two-stage cross-warp reduce + squash + v broadcast; returns vv (t<512)
__device__ __forceinline__ float reduce_squash(
        char* smem_raw, const __half2 s2[8], __half2 v2[8],
        int t, int wid, int lane) {
    __half2* sred  = (__half2*)(smem_raw + SM_SRED);
    __half*  sredh = (__half*)(smem_raw + SM_SRED);   // half view of sred
    float*   ppart = (float*)(smem_raw + SM_PPART);
    __half*  vsm_h = (__half*)(smem_raw + SM_VSM);

#pragma unroll
    for (int j = 0; j < 8; j++)
        sred[j * SRED_ST + wid * 32 + lane] = s2[j];
    __syncthreads();

    // stage B: all 1024 threads; group g sums warps g*16..g*16+15
    const int g = t >> 9, tt = t & 511;
    const int bc = tt >> 4, d = tt & 15, j = d >> 1, par = d & 1;
    float stot = 0.f;
#pragma unroll
    for (int w = 0; w < 16; w++)
        stot += __half2float(sredh[2 * (j * SRED_ST + (g * 16 + w) * 32 + bc) + par]);
    if (g)
        ppart[tt] = stot;
    __syncthreads();

    float vv = 0.f;
    if (t < 512) {
        stot += ppart[tt];
        float magsq = stot * stot;
#pragma unroll
        for (int off = 8; off; off >>= 1)
            magsq += __shfl_xor_sync(0xffffffffu, magsq, off);
        vv = stot * magsq / ((1.f + magsq) * sqrtf(magsq));
        vsm_h[bc * 18 + d] = __float2half_rn(vv);
    }
    __syncthreads();
#pragma unroll
    for (int jj = 0; jj < 8; jj++)
        v2[jj] = *(const __half2*)&vsm_h[lane * 18 + 2 * jj];
    return vv;
}

// ---------------------------------------------------------------------------
// Kernel B: fused 3-pass routing, 1024 threads per location. Warps 0..19
// cache their 180 kka in smem during pass 0; passes 1-2 read LDS. k-loops
// manually software-pipelined (prefetch i+1 before computing i).
// ---------------------------------------------------------------------------
extern __shared__ char smem_raw[];

__global__ void __launch_bounds__(1024, 1) routing_kernel(float* __restrict__ out) {
    float4* cache4 = (float4*)smem_raw;

    const int bl = blockIdx.x;
    const int b = bl / N_LOC, l = bl % N_LOC;
    const int t = threadIdx.x;
    const int wid = t >> 5, lane = t & 31;
    const bool cached = (wid < CACHED_W);

    const float4* po4 = (const float4*)(g_po + (size_t)bl * (N_KKA * 256));

    __half2 v2[8];
    float lgs[9];

    // ---------------- pass 0: c = 1/32, stash cached slices ----------------
    {
        __half2 s2[8];
#pragma unroll
        for (int j = 0; j < 8; j++) s2[j] = __float2half2_rn(0.f);
        const __half2 c2 = __float2half2_rn(0.03125f);

        float4 q0 = po4[wid * 64 + lane];
        float4 q1 = po4[wid * 64 + 32 + lane];
#pragma unroll
        for (int i = 0; i < 9; i++) {
            float4 n0 = q0, n1 = q1;
            if (i < 8) {
                const int kka = (i + 1) * 32 + wid;
                n0 = po4[kka * 64 + lane];
                n1 = po4[kka * 64 + 32 + lane];
            }
            if (cached) {
                const int slot = (i * CACHED_W + wid) * 64;
                cache4[slot + lane]      = q0;
                cache4[slot + 32 + lane] = q1;
            }
            const __half2* h0 = (const __half2*)&q0;
            const __half2* h1 = (const __half2*)&q1;
#pragma unroll
            for (int j = 0; j < 4; j++) {
                s2[j]     = __hfma2(c2, h0[j], s2[j]);
                s2[4 + j] = __hfma2(c2, h1[j], s2[4 + j]);
            }
            q0 = n0; q1 = n1;
        }
        reduce_squash(smem_raw, s2, v2, t, wid, lane);
    }

    // ---------------- passes 1 and 2 ----------------
    float vout = 0.f;
#pragma unroll 1
    for (int pass = 1; pass < 3; pass++) {
        __half2 s2[8];
#pragma unroll
        for (int j = 0; j < 8; j++) s2[j] = __float2half2_rn(0.f);

        float4 q0, q1;
        if (cached) {
            const int slot = wid * 64;
            q0 = cache4[slot + lane];
            q1 = cache4[slot + 32 + lane];
        } else {
            q0 = po4[wid * 64 + lane];
            q1 = po4[wid * 64 + 32 + lane];
        }
#pragma unroll
        for (int i = 0; i < 9; i++) {
            float4 n0 = q0, n1 = q1;
            if (i < 8) {
                if (cached) {
                    const int slot = ((i + 1) * CACHED_W + wid) * 64;
                    n0 = cache4[slot + lane];
                    n1 = cache4[slot + 32 + lane];
                } else {
                    const int kka = (i + 1) * 32 + wid;
                    n0 = po4[kka * 64 + lane];
                    n1 = po4[kka * 64 + 32 + lane];
                }
            }
            __half2 r2[8];
            {
                const __half2* h0 = (const __half2*)&q0;
                const __half2* h1 = (const __half2*)&q1;
#pragma unroll
                for (int j = 0; j < 4; j++) { r2[j] = h0[j]; r2[4 + j] = h1[j]; }
            }
            __half2 acc0 = __hmul2(v2[0], r2[0]);
            acc0 = __hfma2(v2[1], r2[1], acc0);
            acc0 = __hfma2(v2[2], r2[2], acc0);
            acc0 = __hfma2(v2[3], r2[3], acc0);
            __half2 acc1 = __hmul2(v2[4], r2[4]);
            acc1 = __hfma2(v2[5], r2[5], acc1);
            acc1 = __hfma2(v2[6], r2[6], acc1);
            acc1 = __hfma2(v2[7], r2[7], acc1);
            const float2 df = __half22float2(__hadd2(acc0, acc1));
            const float delta = df.x + df.y;
            const float lg = (pass == 2) ? (lgs[i] + delta) : delta;
            lgs[i] = lg;
            const __half2 c2 = __half2half2(__float2half_rn(softmax_c(lg)));
#pragma unroll
            for (int j = 0; j < 8; j++) s2[j] = __hfma2(c2, r2[j], s2[j]);
            q0 = n0; q1 = n1;
        }

        const float vv = reduce_squash(smem_raw, s2, v2, t, wid, lane);
        if (pass == 2) vout = vv;
    }

    if (t < 512)
        out[((size_t)b * N_P + t) * N_LOC + l] = vout;
}

// ---------------------------------------------------------------------------
extern "C" void kernel_launch(void* const* d_in, const int* in_sizes, int n_in,
                              void* d_out, int out_size) {
    const float* pose = (const float*)d_in[0];  // (4, 256, 14, 14)
    const float* W    = (const float*)d_in[1];  // (288, 512, 8)
    float* out = (float*)d_out;                 // (4, 512, 14, 14)

    cudaFuncSetAttribute(routing_kernel,
                         cudaFuncAttributeMaxDynamicSharedMemorySize, SM_TOTAL);

    pose_out_kernel<<<dim3(N_KKA, N_BL / TILE), 256>>>(pose, W);
    routing_kernel<<<N_BL, 1024, SM_TOTAL>>>(out);
}

// round 11
// speedup vs baseline: 2.4272x; 1.1210x over previous
#include <cuda_runtime.h>
#include <cuda_fp16.h>

#define N_KKA 288
#define N_P   512
#define N_LOC 196
#define N_BL  784   // 4 * 196
#define TILE  56    // bl per kernel-A CTA (784 = 56*14)

#define CACHED_W 21          // warps 0..20 cache their po slice in smem
#define SRED_ST  1026        // h2 stride

typedef unsigned long long ull;

// 231 MB fp16 scratch, chunk-interleaved: half index =
//   kka*512 + j*256 + bc*8 + dd   (d = j*8+dd, j=0..1)
__device__ __half2 g_po[(size_t)N_BL * N_KKA * 256];

__device__ __forceinline__ ull ffma2(ull a, ull b, ull c) {
    ull d;
    asm("fma.rn.f32x2 %0, %1, %2, %3;" : "=l"(d) : "l"(a), "l"(b), "l"(c));
    return d;
}
__device__ __forceinline__ ull pack2(float lo, float hi) {
    ull d;
    asm("mov.b64 %0, {%1, %2};" : "=l"(d) : "f"(lo), "f"(hi));
    return d;
}
__device__ __forceinline__ void unpack2(float& lo, float& hi, ull v) {
    asm("mov.b64 {%0, %1}, %2;" : "=f"(lo), "=f"(hi) : "l"(v));
}
__device__ __forceinline__ void cp_async16(unsigned saddr, const void* gptr) {
    asm volatile("cp.async.cg.shared.global [%0], [%1], 16;"
                 :: "r"(saddr), "l"(gptr));
}

// ---------------------------------------------------------------------------
// Kernel A: unchanged (write-stream bound).
// ---------------------------------------------------------------------------
__global__ void __launch_bounds__(256) pose_out_kernel(
        const float* __restrict__ pose, const float* __restrict__ W) {
    const int kka  = blockIdx.x;
    const int tile = blockIdx.y;
    __shared__ float Wsm[N_P * 9];
    __shared__ float xsmT[8 * TILE];   // [c][blc]
    const int t = threadIdx.x;

    const float4* Wk4 = (const float4*)(W + (size_t)kka * (N_P * 8));
#pragma unroll
    for (int j = 0; j < 4; j++) {
        const int i4 = t + j * 256;
        const float4 w4 = Wk4[i4];
        const int p = i4 >> 1;
        const int cb = (i4 & 1) * 4;
        const int slot = ((p & 1) << 8) | ((p >> 4) << 3) | ((p & 15) >> 1);
        Wsm[slot * 9 + cb + 0] = w4.x;
        Wsm[slot * 9 + cb + 1] = w4.y;
        Wsm[slot * 9 + cb + 2] = w4.z;
        Wsm[slot * 9 + cb + 3] = w4.w;
    }

    const int a = kka & 31, kk = kka >> 5;
    const int ky = kk / 3, kx = kk % 3;
#pragma unroll
    for (int idx = t; idx < TILE * 8; idx += 256) {
        const int blc = idx >> 3, c = idx & 7;
        const int bl = tile * TILE + blc;
        const int b = bl / N_LOC, l = bl % N_LOC;
        const int oh = l / 14, ow = l % 14;
        const int ih = oh + ky - 1, iw = ow + kx - 1;
        float val = 0.f;
        if ((unsigned)ih < 14u && (unsigned)iw < 14u)
            val = pose[((b * 256 + a * 8 + c) * 14 + ih) * 14 + iw];
        xsmT[c * TILE + blc] = val;
    }
    __syncthreads();

    ull wd0[8], wd1[8];
#pragma unroll
    for (int c = 0; c < 8; c++) {
        const float a0 = Wsm[t * 9 + c];
        const float a1 = Wsm[(t + 256) * 9 + c];
        wd0[c] = pack2(a0, a0);
        wd1[c] = pack2(a1, a1);
    }
    const int slot_t = ((t & 4) << 5) | ((t >> 3) << 2) | (t & 3);
    __half2* dstbase = g_po + ((size_t)(tile * TILE) * N_KKA + kka) * 256 + slot_t;
#pragma unroll 2
    for (int pair = 0; pair < TILE / 2; pair++) {
        ull acc0 = 0ull, acc1 = 0ull;
#pragma unroll
        for (int c = 0; c < 8; c++) {
            const ull x2 = *(const ull*)&xsmT[c * TILE + pair * 2];
            acc0 = ffma2(wd0[c], x2, acc0);
            acc1 = ffma2(wd1[c], x2, acc1);
        }
        float a0A, a0B, a1A, a1B;
        unpack2(a0A, a0B, acc0);
        unpack2(a1A, a1B, acc1);
        __half2* dstA = dstbase + (size_t)(pair * 2) * (N_KKA * 256);
        __half2* dstB = dstA + (N_KKA * 256);
        *dstA = __floats2half2_rn(a0A, a1A);
        *dstB = __floats2half2_rn(a0B, a1B);
    }
}

// ---------------------------------------------------------------------------
// Kernel B helpers
// ---------------------------------------------------------------------------
__device__ __forceinline__ float softmax_c(float lg) {
    float es;
    {
        const float x = fmaf(lg, 1.44269504f, 16.0f);
        asm("ex2.approx.f32 %0, %1;" : "=f"(es) : "f"(x));
    }
    const unsigned ei = __float2uint_rn(es);
    unsigned si;
    asm("redux.sync.add.u32 %0, %1, 0xffffffff;" : "=r"(si) : "r"(ei));
    return __fdividef(es, __uint2float_rn(si));
}

// smem layout (bytes):
//   cache4 : 0        .. 193536   (9*21 kka slices * 1KB)
//   sred   : 193536   .. +32832 -> 226368
//   ppart  : 226368   .. +2048  -> 228416   (512 floats)
//   vsm    : 228416   .. +1152  -> 229568   (32 bc * 18 halves)
#define SM_SRED  193536
#define SM_PPART 226368
#define SM_VSM   228416
#define SM_TOTAL 229568

// two-stage cross-warp reduce + squash + v broadcast; returns vv (t<512)
__device__ __forceinline__ float reduce_squash(
        char* smem_raw, const __half2 s2[8], __half2 v2[8],
        int t, int wid, int lane) {
    __half2* sred  = (__half2*)(smem_raw + SM_SRED);
    __half*  sredh = (__half*)(smem_raw + SM_SRED);
    float*   ppart = (float*)(smem_raw + SM_PPART);
    __half*  vsm_h = (__half*)(smem_raw + SM_VSM);

#pragma unroll
    for (int j = 0; j < 8; j++)
        sred[j * SRED_ST + wid * 32 + lane] = s2[j];
    __syncthreads();

    const int g = t >> 9, tt = t & 511;
    const int bc = tt >> 4, d = tt & 15, j = d >> 1, par = d & 1;
    float stot = 0.f;
#pragma unroll
    for (int w = 0; w < 16; w++)
        stot += __half2float(sredh[2 * (j * SRED_ST + (g * 16 + w) * 32 + bc) + par]);
    if (g)
        ppart[tt] = stot;
    __syncthreads();

    float vv = 0.f;
    if (t < 512) {
        stot += ppart[tt];
        float magsq = stot * stot;
#pragma unroll
        for (int off = 8; off; off >>= 1)
            magsq += __shfl_xor_sync(0xffffffffu, magsq, off);
        vv = stot * magsq / ((1.f + magsq) * sqrtf(magsq));
        vsm_h[bc * 18 + d] = __float2half_rn(vv);
    }
    __syncthreads();
#pragma unroll
    for (int jj = 0; jj < 8; jj++)
        v2[jj] = *(const __half2*)&vsm_h[lane * 18 + 2 * jj];
    return vv;
}

// ---------------------------------------------------------------------------
// Kernel B: fused 3-pass routing, 1024 threads per location.
// Pass 0: cached warps (0..20) fill their smem slices via cp.async (18
// outstanding 16B copies, register-free MLP), then accumulate from smem;
// uncached warps use the pipelined-LDG path. Passes 1-2 as round 10.
// ---------------------------------------------------------------------------
extern __shared__ char smem_raw[];

__global__ void __launch_bounds__(1024, 1) routing_kernel(float* __restrict__ out) {
    float4* cache4 = (float4*)smem_raw;

    const int bl = blockIdx.x;
    const int b = bl / N_LOC, l = bl % N_LOC;
    const int t = threadIdx.x;
    const int wid = t >> 5, lane = t & 31;
    const bool cached = (wid < CACHED_W);

    const float4* po4 = (const float4*)(g_po + (size_t)bl * (N_KKA * 256));

    __half2 v2[8];
    float lgs[9];

    // ---------------- pass 0: c = 1/32 ----------------
    {
        __half2 s2[8];
#pragma unroll
        for (int j = 0; j < 8; j++) s2[j] = __float2half2_rn(0.f);
        const __half2 c2 = __float2half2_rn(0.03125f);

        if (cached) {
            // register-free deep-MLP fill of this warp's 9 slices
            const unsigned cbase = (unsigned)__cvta_generic_to_shared(cache4);
#pragma unroll
            for (int i = 0; i < 9; i++) {
                const int kka = i * 32 + wid;
                const unsigned dst = cbase + (unsigned)(((i * CACHED_W + wid) * 64 + lane) * 16);
                cp_async16(dst,       po4 + kka * 64 + lane);
                cp_async16(dst + 512, po4 + kka * 64 + 32 + lane);
            }
            asm volatile("cp.async.commit_group;");
            asm volatile("cp.async.wait_group 0;" ::: "memory");
            // accumulate from smem (own addresses -> no barrier needed)
#pragma unroll
            for (int i = 0; i < 9; i++) {
                const int slot = (i * CACHED_W + wid) * 64;
                const float4 q0 = cache4[slot + lane];
                const float4 q1 = cache4[slot + 32 + lane];
                const __half2* h0 = (const __half2*)&q0;
                const __half2* h1 = (const __half2*)&q1;
#pragma unroll
                for (int j = 0; j < 4; j++) {
                    s2[j]     = __hfma2(c2, h0[j], s2[j]);
                    s2[4 + j] = __hfma2(c2, h1[j], s2[4 + j]);
                }
            }
        } else {
            float4 q0 = po4[wid * 64 + lane];
            float4 q1 = po4[wid * 64 + 32 + lane];
#pragma unroll
            for (int i = 0; i < 9; i++) {
                float4 n0 = q0, n1 = q1;
                if (i < 8) {
                    const int kka = (i + 1) * 32 + wid;
                    n0 = po4[kka * 64 + lane];
                    n1 = po4[kka * 64 + 32 + lane];
                }
                const __half2* h0 = (const __half2*)&q0;
                const __half2* h1 = (const __half2*)&q1;
#pragma unroll
                for (int j = 0; j < 4; j++) {
                    s2[j]     = __hfma2(c2, h0[j], s2[j]);
                    s2[4 + j] = __hfma2(c2, h1[j], s2[4 + j]);
                }
                q0 = n0; q1 = n1;
            }
        }
        reduce_squash(smem_raw, s2, v2, t, wid, lane);
    }

    // ---------------- passes 1 and 2 ----------------
    float vout = 0.f;
#pragma unroll 1
    for (int pass = 1; pass < 3; pass++) {
        __half2 s2[8];
#pragma unroll
        for (int j = 0; j < 8; j++) s2[j] = __float2half2_rn(0.f);

        float4 q0, q1;
        if (cached) {
            const int slot = wid * 64;
            q0 = cache4[slot + lane];
            q1 = cache4[slot + 32 + lane];
        } else {
            q0 = po4[wid * 64 + lane];
            q1 = po4[wid * 64 + 32 + lane];
        }
#pragma unroll
        for (int i = 0; i < 9; i++) {
            float4 n0 = q0, n1 = q1;
            if (i < 8) {
                if (cached) {
                    const int slot = ((i + 1) * CACHED_W + wid) * 64;
                    n0 = cache4[slot + lane];
                    n1 = cache4[slot + 32 + lane];
                } else {
                    const int kka = (i + 1) * 32 + wid;
                    n0 = po4[kka * 64 + lane];
                    n1 = po4[kka * 64 + 32 + lane];
                }
            }
            __half2 r2[8];
            {
                const __half2* h0 = (const __half2*)&q0;
                const __half2* h1 = (const __half2*)&q1;
#pragma unroll
                for (int j = 0; j < 4; j++) { r2[j] = h0[j]; r2[4 + j] = h1[j]; }
            }
            __half2 acc0 = __hmul2(v2[0], r2[0]);
            acc0 = __hfma2(v2[1], r2[1], acc0);
            acc0 = __hfma2(v2[2], r2[2], acc0);
            acc0 = __hfma2(v2[3], r2[3], acc0);
            __half2 acc1 = __hmul2(v2[4], r2[4]);
            acc1 = __hfma2(v2[5], r2[5], acc1);
            acc1 = __hfma2(v2[6], r2[6], acc1);
            acc1 = __hfma2(v2[7], r2[7], acc1);
            const float2 df = __half22float2(__hadd2(acc0, acc1));
            const float delta = df.x + df.y;
            const float lg = (pass == 2) ? (lgs[i] + delta) : delta;
            lgs[i] = lg;
            const __half2 c2 = __half2half2(__float2half_rn(softmax_c(lg)));
#pragma unroll
            for (int j = 0; j < 8; j++) s2[j] = __hfma2(c2, r2[j], s2[j]);
            q0 = n0; q1 = n1;
        }

        const float vv = reduce_squash(smem_raw, s2, v2, t, wid, lane);
        if (pass == 2) vout = vv;
    }

    if (t < 512)
        out[((size_t)b * N_P + t) * N_LOC + l] = vout;
}

// ---------------------------------------------------------------------------
extern "C" void kernel_launch(void* const* d_in, const int* in_sizes, int n_in,
                              void* d_out, int out_size) {
    const float* pose = (const float*)d_in[0];  // (4, 256, 14, 14)
    const float* W    = (const float*)d_in[1];  // (288, 512, 8)
    float* out = (float*)d_out;                 // (4, 512, 14, 14)

    cudaFuncSetAttribute(routing_kernel,
                         cudaFuncAttributeMaxDynamicSharedMemorySize, SM_TOTAL);

    pose_out_kernel<<<dim3(N_KKA, N_BL / TILE), 256>>>(pose, W);
    routing_kernel<<<N_BL, 1024, SM_TOTAL>>>(out);
}

// round 12
// speedup vs baseline: 2.5417x; 1.0472x over previous
#include <cuda_runtime.h>
#include <cuda_fp16.h>

#define N_KKA 288
#define N_P   512
#define N_LOC 196
#define N_BL  784   // 4 * 196
#define TILE  56    // bl per kernel-A CTA (784 = 56*14)

#define CACHED_I 5           // i < 5 slices cached in smem (80 of 288 kka)
#define SRED_ST  514         // h2 stride (16 warps * 32 + 2 pad)

typedef unsigned long long ull;

// 231 MB fp16 scratch, chunk-interleaved: half index =
//   kka*512 + j*256 + bc*8 + dd   (d = j*8+dd, j=0..1)
__device__ __half2 g_po[(size_t)N_BL * N_KKA * 256];

__device__ __forceinline__ ull ffma2(ull a, ull b, ull c) {
    ull d;
    asm("fma.rn.f32x2 %0, %1, %2, %3;" : "=l"(d) : "l"(a), "l"(b), "l"(c));
    return d;
}
__device__ __forceinline__ ull pack2(float lo, float hi) {
    ull d;
    asm("mov.b64 %0, {%1, %2};" : "=l"(d) : "f"(lo), "f"(hi));
    return d;
}
__device__ __forceinline__ void unpack2(float& lo, float& hi, ull v) {
    asm("mov.b64 {%0, %1}, %2;" : "=f"(lo), "=f"(hi) : "l"(v));
}
__device__ __forceinline__ void cp_async16(unsigned saddr, const void* gptr) {
    asm volatile("cp.async.cg.shared.global [%0], [%1], 16;"
                 :: "r"(saddr), "l"(gptr));
}

// ---------------------------------------------------------------------------
// Kernel A: unchanged (write-stream bound).
// ---------------------------------------------------------------------------
__global__ void __launch_bounds__(256) pose_out_kernel(
        const float* __restrict__ pose, const float* __restrict__ W) {
    const int kka  = blockIdx.x;
    const int tile = blockIdx.y;
    __shared__ float Wsm[N_P * 9];
    __shared__ float xsmT[8 * TILE];   // [c][blc]
    const int t = threadIdx.x;

    const float4* Wk4 = (const float4*)(W + (size_t)kka * (N_P * 8));
#pragma unroll
    for (int j = 0; j < 4; j++) {
        const int i4 = t + j * 256;
        const float4 w4 = Wk4[i4];
        const int p = i4 >> 1;
        const int cb = (i4 & 1) * 4;
        const int slot = ((p & 1) << 8) | ((p >> 4) << 3) | ((p & 15) >> 1);
        Wsm[slot * 9 + cb + 0] = w4.x;
        Wsm[slot * 9 + cb + 1] = w4.y;
        Wsm[slot * 9 + cb + 2] = w4.z;
        Wsm[slot * 9 + cb + 3] = w4.w;
    }

    const int a = kka & 31, kk = kka >> 5;
    const int ky = kk / 3, kx = kk % 3;
#pragma unroll
    for (int idx = t; idx < TILE * 8; idx += 256) {
        const int blc = idx >> 3, c = idx & 7;
        const int bl = tile * TILE + blc;
        const int b = bl / N_LOC, l = bl % N_LOC;
        const int oh = l / 14, ow = l % 14;
        const int ih = oh + ky - 1, iw = ow + kx - 1;
        float val = 0.f;
        if ((unsigned)ih < 14u && (unsigned)iw < 14u)
            val = pose[((b * 256 + a * 8 + c) * 14 + ih) * 14 + iw];
        xsmT[c * TILE + blc] = val;
    }
    __syncthreads();

    ull wd0[8], wd1[8];
#pragma unroll
    for (int c = 0; c < 8; c++) {
        const float a0 = Wsm[t * 9 + c];
        const float a1 = Wsm[(t + 256) * 9 + c];
        wd0[c] = pack2(a0, a0);
        wd1[c] = pack2(a1, a1);
    }
    const int slot_t = ((t & 4) << 5) | ((t >> 3) << 2) | (t & 3);
    __half2* dstbase = g_po + ((size_t)(tile * TILE) * N_KKA + kka) * 256 + slot_t;
#pragma unroll 2
    for (int pair = 0; pair < TILE / 2; pair++) {
        ull acc0 = 0ull, acc1 = 0ull;
#pragma unroll
        for (int c = 0; c < 8; c++) {
            const ull x2 = *(const ull*)&xsmT[c * TILE + pair * 2];
            acc0 = ffma2(wd0[c], x2, acc0);
            acc1 = ffma2(wd1[c], x2, acc1);
        }
        float a0A, a0B, a1A, a1B;
        unpack2(a0A, a0B, acc0);
        unpack2(a1A, a1B, acc1);
        __half2* dstA = dstbase + (size_t)(pair * 2) * (N_KKA * 256);
        __half2* dstB = dstA + (N_KKA * 256);
        *dstA = __floats2half2_rn(a0A, a1A);
        *dstB = __floats2half2_rn(a0B, a1B);
    }
}

// ---------------------------------------------------------------------------
// Kernel B helpers
// ---------------------------------------------------------------------------
__device__ __forceinline__ float softmax_c(float lg) {
    float es;
    {
        const float x = fmaf(lg, 1.44269504f, 16.0f);
        asm("ex2.approx.f32 %0, %1;" : "=f"(es) : "f"(x));
    }
    const unsigned ei = __float2uint_rn(es);
    unsigned si;
    asm("redux.sync.add.u32 %0, %1, 0xffffffff;" : "=r"(si) : "r"(ei));
    return __fdividef(es, __uint2float_rn(si));
}

// smem layout (bytes), 512-thread CTA (2 CTAs/SM):
//   cache4 : 0     .. 81920    (80 kka slices * 1KB, i<5 all 16 warps)
//   sred   : 81920 .. +8*514*4 = 16448 -> 98368
//   vsm    : 98368 .. +1152 -> 99520    (32 bc * 18 halves)
#define SM_SRED  81920
#define SM_VSM   98368
#define SM_TOTAL 99520

// 16-warp cross-warp reduce + squash; writes v into vsm, returns vv
__device__ __forceinline__ float reduce_squash16(
        char* smem_raw, const __half2 s2[8], int t, int wid, int lane) {
    __half2* sred  = (__half2*)(smem_raw + SM_SRED);
    __half*  sredh = (__half*)(smem_raw + SM_SRED);
    __half*  vsm_h = (__half*)(smem_raw + SM_VSM);

#pragma unroll
    for (int j = 0; j < 8; j++)
        sred[j * SRED_ST + wid * 32 + lane] = s2[j];
    __syncthreads();

    const int bc = t >> 4, d = t & 15, j = d >> 1, par = d & 1;
    float stot = 0.f;
#pragma unroll
    for (int w = 0; w < 16; w++)
        stot += __half2float(sredh[2 * (j * SRED_ST + w * 32 + bc) + par]);

    float magsq = stot * stot;
#pragma unroll
    for (int off = 8; off; off >>= 1)
        magsq += __shfl_xor_sync(0xffffffffu, magsq, off);
    const float vv = stot * magsq / ((1.f + magsq) * sqrtf(magsq));
    vsm_h[bc * 18 + d] = __float2half_rn(vv);
    __syncthreads();
    return vv;
}

// ---------------------------------------------------------------------------
// Kernel B: fused 3-pass routing, 512 threads/CTA, 2 CTAs/SM so one CTA's
// DRAM-bound pass 0 overlaps the other's compute passes. Warp wid handles
// kka = i*16 + wid, i=0..17. i<5 cached in smem (cp.async fill in pass 0).
// Logits never stored: logit_p = (sum of all previous v)·po  (vsum trick).
// ---------------------------------------------------------------------------
extern __shared__ char smem_raw[];

__global__ void __launch_bounds__(512, 2) routing_kernel(float* __restrict__ out) {
    float4* cache4 = (float4*)smem_raw;
    __half* vsm_h  = (__half*)(smem_raw + SM_VSM);

    const int bl = blockIdx.x;
    const int b = bl / N_LOC, l = bl % N_LOC;
    const int t = threadIdx.x;
    const int wid = t >> 5, lane = t & 31;

    const float4* po4 = (const float4*)(g_po + (size_t)bl * (N_KKA * 256));

    __half2 vsum2[8];   // running sum of v over completed passes
    float vout = 0.f;

    // ---------------- pass 0: c = 1/32; fill cache via cp.async ----------------
    {
        __half2 s2[8];
#pragma unroll
        for (int j = 0; j < 8; j++) s2[j] = __float2half2_rn(0.f);
        const __half2 c2 = __float2half2_rn(0.03125f);

        const unsigned cbase = (unsigned)__cvta_generic_to_shared(cache4);
#pragma unroll
        for (int i = 0; i < CACHED_I; i++) {
            const int kka = i * 16 + wid;
            const unsigned dst = cbase + (unsigned)((kka * 64 + lane) * 16);
            cp_async16(dst,       po4 + kka * 64 + lane);
            cp_async16(dst + 512, po4 + kka * 64 + 32 + lane);
        }
        asm volatile("cp.async.commit_group;");

        // pipelined LDG for i = 5..17 (overlaps the cp.async fill)
        float4 q0 = po4[(CACHED_I * 16 + wid) * 64 + lane];
        float4 q1 = po4[(CACHED_I * 16 + wid) * 64 + 32 + lane];
#pragma unroll
        for (int i = CACHED_I; i < 18; i++) {
            float4 n0 = q0, n1 = q1;
            if (i < 17) {
                const int kka = (i + 1) * 16 + wid;
                n0 = po4[kka * 64 + lane];
                n1 = po4[kka * 64 + 32 + lane];
            }
            const __half2* h0 = (const __half2*)&q0;
            const __half2* h1 = (const __half2*)&q1;
#pragma unroll
            for (int j = 0; j < 4; j++) {
                s2[j]     = __hfma2(c2, h0[j], s2[j]);
                s2[4 + j] = __hfma2(c2, h1[j], s2[4 + j]);
            }
            q0 = n0; q1 = n1;
        }

        asm volatile("cp.async.wait_group 0;" ::: "memory");
#pragma unroll
        for (int i = 0; i < CACHED_I; i++) {
            const int slot = (i * 16 + wid) * 64;
            const float4 c0 = cache4[slot + lane];
            const float4 c1 = cache4[slot + 32 + lane];
            const __half2* h0 = (const __half2*)&c0;
            const __half2* h1 = (const __half2*)&c1;
#pragma unroll
            for (int j = 0; j < 4; j++) {
                s2[j]     = __hfma2(c2, h0[j], s2[j]);
                s2[4 + j] = __hfma2(c2, h1[j], s2[4 + j]);
            }
        }

        reduce_squash16(smem_raw, s2, t, wid, lane);
        const __half2* vh2 = (const __half2*)vsm_h;
#pragma unroll
        for (int j = 0; j < 8; j++)
            vsum2[j] = *(const __half2*)&vsm_h[lane * 18 + 2 * j];
    }

    // ---------------- passes 1 and 2: logit = vsum . r ----------------
#pragma unroll 1
    for (int pass = 1; pass < 3; pass++) {
        __half2 s2[8];
#pragma unroll
        for (int j = 0; j < 8; j++) s2[j] = __float2half2_rn(0.f);

        float4 q0 = cache4[wid * 64 + lane];
        float4 q1 = cache4[wid * 64 + 32 + lane];
#pragma unroll
        for (int i = 0; i < 18; i++) {
            float4 n0 = q0, n1 = q1;
            if (i < 17) {
                const int ii = i + 1;
                if (ii < CACHED_I) {
                    const int slot = (ii * 16 + wid) * 64;
                    n0 = cache4[slot + lane];
                    n1 = cache4[slot + 32 + lane];
                } else {
                    const int kka = ii * 16 + wid;
                    n0 = po4[kka * 64 + lane];
                    n1 = po4[kka * 64 + 32 + lane];
                }
            }
            __half2 r2[8];
            {
                const __half2* h0 = (const __half2*)&q0;
                const __half2* h1 = (const __half2*)&q1;
#pragma unroll
                for (int j = 0; j < 4; j++) { r2[j] = h0[j]; r2[4 + j] = h1[j]; }
            }
            __half2 acc0 = __hmul2(vsum2[0], r2[0]);
            acc0 = __hfma2(vsum2[1], r2[1], acc0);
            acc0 = __hfma2(vsum2[2], r2[2], acc0);
            acc0 = __hfma2(vsum2[3], r2[3], acc0);
            __half2 acc1 = __hmul2(vsum2[4], r2[4]);
            acc1 = __hfma2(vsum2[5], r2[5], acc1);
            acc1 = __hfma2(vsum2[6], r2[6], acc1);
            acc1 = __hfma2(vsum2[7], r2[7], acc1);
            const float2 df = __half22float2(__hadd2(acc0, acc1));
            const float lg = df.x + df.y;
            const __half2 c2 = __half2half2(__float2half_rn(softmax_c(lg)));
#pragma unroll
            for (int j = 0; j < 8; j++) s2[j] = __hfma2(c2, r2[j], s2[j]);
            q0 = n0; q1 = n1;
        }

        const float vv = reduce_squash16(smem_raw, s2, t, wid, lane);
        if (pass == 2) {
            vout = vv;
        } else {
#pragma unroll
            for (int j = 0; j < 8; j++)
                vsum2[j] = __hadd2(vsum2[j],
                                   *(const __half2*)&vsm_h[lane * 18 + 2 * j]);
        }
    }

    // out[b, p = t, l]
    out[((size_t)b * N_P + t) * N_LOC + l] = vout;
}

// ---------------------------------------------------------------------------
extern "C" void kernel_launch(void* const* d_in, const int* in_sizes, int n_in,
                              void* d_out, int out_size) {
    const float* pose = (const float*)d_in[0];  // (4, 256, 14, 14)
    const float* W    = (const float*)d_in[1];  // (288, 512, 8)
    float* out = (float*)d_out;                 // (4, 512, 14, 14)

    cudaFuncSetAttribute(routing_kernel,
                         cudaFuncAttributeMaxDynamicSharedMemorySize, SM_TOTAL);

    pose_out_kernel<<<dim3(N_KKA, N_BL / TILE), 256>>>(pose, W);
    routing_kernel<<<N_BL, 512, SM_TOTAL>>>(out);
}